// round 1
// baseline (speedup 1.0000x reference)
#include <cuda_runtime.h>
#include <math.h>

#define B_ 8
#define C_ 12
#define S_ 784
#define N_ 785
#define D_ 768
#define H_ 28
#define PATCHNUM 84

// ---------------- scratch (static __device__, no allocs) ----------------
__device__ float g_newscore[B_ * C_ * S_];
__device__ int   g_count[B_ * S_];
__device__ __align__(16) float g_struct[B_ * D_];
__device__ int   g_patch[B_ * 64];
struct BSc { float c0, c1, Ppos, Pneg, pwa; int anchor; };
__device__ BSc g_bs[B_];

// ---------------- K0: zero the count buffer (graph replays must be deterministic)
__global__ void k_zero() {
    int i = blockIdx.x * blockDim.x + threadIdx.x;
    if (i < B_ * S_) g_count[i] = 0;
}

// ---------------- K1: per (b,c) top-84 select + new_score + count scatter
__global__ void k_score(const float* __restrict__ x) {
    int bc = blockIdx.x;           // b*C + c, 96 blocks
    int s  = threadIdx.x;          // 784 threads
    __shared__ float sc[S_];
    float v = x[(size_t)bc * N_ * N_ + 1 + s];   // x[b,c,0,1+s]
    sc[s] = v;
    __syncthreads();
    int r = 0;
    #pragma unroll 8
    for (int t = 0; t < S_; t++) {
        float o = sc[t];
        r += (o > v) || (o == v && t < s);
    }
    bool sel = (r < PATCHNUM);
    g_newscore[bc * S_ + s] = sel ? v : 0.7f * v;
    if (sel) atomicAdd(&g_count[(bc / C_) * S_ + s], 1);
}

// ---------------- K2: per-batch reductions -> anchor, c0,c1,Ppos,Pneg,pw_anchor
__global__ void k_batch() {
    int b = blockIdx.x, tid = threadIdx.x;      // 1024 threads
    __shared__ float pw[S_];
    __shared__ float red[1024];
    __shared__ int   redi[1024];

    float m = 0.f;
    if (tid < S_) {
        #pragma unroll
        for (int c = 0; c < C_; c++) m += g_newscore[(b * C_ + c) * S_ + tid];
        pw[tid] = m / 12.0f;
    }
    // sum of m -> mean
    red[tid] = (tid < S_) ? m : 0.f;
    __syncthreads();
    for (int st = 512; st > 0; st >>= 1) {
        if (tid < st) red[tid] += red[tid + st];
        __syncthreads();
    }
    float mean = red[0] / 784.0f;
    __syncthreads();

    // argmax of binary*pw (first index on ties)
    float masked = -1e30f;
    if (tid < S_) masked = (m > mean) ? pw[tid] : 0.0f;
    red[tid] = masked; redi[tid] = tid;
    __syncthreads();
    for (int st = 512; st > 0; st >>= 1) {
        if (tid < st) {
            if (red[tid + st] > red[tid] ||
                (red[tid + st] == red[tid] && redi[tid + st] < redi[tid])) {
                red[tid] = red[tid + st]; redi[tid] = redi[tid + st];
            }
        }
        __syncthreads();
    }
    int anchor = redi[0];
    __syncthreads();

    // structure sums
    float p = 0.f, d = 0.f, a = 0.f;
    if (tid < S_) {
        p = pw[tid];
        int ai = anchor / H_, aj = anchor % H_;
        float r0 = (float)(tid / H_ - ai) / (float)H_;
        float r1 = (float)(tid % H_ - aj) / (float)H_;
        d = sqrtf(r0 * r0 + r1 * r1);
        a = (atan2f(r1, r0) / 3.14159265358979323846f + 1.0f) * 0.5f;
    }
    float vals[4] = { p * d, p * a, (p > 0.f) ? p * p : 0.f, (p < 0.f) ? p * p : 0.f };
    float out4[4];
    #pragma unroll
    for (int k = 0; k < 4; k++) {
        red[tid] = (tid < S_) ? vals[k] : 0.f;
        __syncthreads();
        for (int st = 512; st > 0; st >>= 1) {
            if (tid < st) red[tid] += red[tid + st];
            __syncthreads();
        }
        out4[k] = red[0];
        __syncthreads();
    }
    if (tid == 0) {
        BSc bs;
        bs.c0 = out4[0]; bs.c1 = out4[1]; bs.Ppos = out4[2]; bs.Pneg = out4[3];
        bs.pwa = pw[anchor]; bs.anchor = anchor;
        g_bs[b] = bs;
    }
}

// ---------------- K3: collapsed GCN -> struct row at anchor (per batch)
__global__ void k_gcn(const float* __restrict__ w1, const float* __restrict__ w2) {
    int b = blockIdx.x, tid = threadIdx.x;   // 768 threads
    __shared__ float u[512];
    BSc bs = g_bs[b];
    if (tid < 512) {
        float v = bs.c0 * w1[tid] + bs.c1 * w1[512 + tid];
        u[tid] = bs.Ppos * fmaxf(v, 0.f) + bs.Pneg * fminf(v, 0.f);
    }
    __syncthreads();
    float acc = 0.f;
    #pragma unroll 8
    for (int j = 0; j < 512; j++) acc += u[j] * w2[j * D_ + tid];
    float o = bs.pwa * acc;
    g_struct[b * D_ + tid] = (o > 0.f) ? o : 0.2f * o;
}

// ---------------- K4: hs = hidden_states; hs[:,0] += struct  (vectorized copy)
__global__ void k_hs(const float4* __restrict__ hid, float4* __restrict__ out) {
    const int TOT4 = B_ * N_ * (D_ / 4);   // 1,205,760
    int i = blockIdx.x * blockDim.x + threadIdx.x;
    if (i >= TOT4) return;
    float4 v = hid[i];
    int row = i / (D_ / 4);
    int n = row % N_;
    if (n == 0) {
        int b  = row / N_;
        int d4 = i % (D_ / 4);
        float4 sv = ((const float4*)g_struct)[b * (D_ / 4) + d4];
        v.x += sv.x; v.y += sv.y; v.z += sv.z; v.w += sv.w;
    }
    out[i] = v;
}

// ---------------- K5: 3x3 conv of counts + exact stable-descending rank -> patch_idx
__global__ void k_order(int select_num) {
    int b = blockIdx.x, s = threadIdx.x;   // 784 threads
    __shared__ int cnt[S_];
    __shared__ int conv[S_];
    cnt[s] = g_count[b * S_ + s];
    __syncthreads();
    int i = s / H_, j = s % H_;
    int acc = 0;
    #pragma unroll
    for (int di = -1; di <= 1; di++) {
        #pragma unroll
        for (int dj = -1; dj <= 1; dj++) {
            int ii = i + di, jj = j + dj;
            if (ii >= 0 && ii < H_ && jj >= 0 && jj < H_) {
                int w = (di == 0 ? 2 : 1) * (dj == 0 ? 2 : 1);
                acc += w * cnt[ii * H_ + jj];
            }
        }
    }
    conv[s] = acc;
    __syncthreads();
    int r = 0;
    #pragma unroll 8
    for (int t = 0; t < S_; t++) {
        int o = conv[t];
        r += (o > acc) || (o == acc && t < s);
    }
    if (r < select_num && r < 64) g_patch[b * 64 + r] = s + 1;
}

// ---------------- K6: gather selected rows (indices >= 1, so raw hidden_states)
__global__ void k_gather(const float4* __restrict__ hid, float4* __restrict__ out_sel,
                         int select_num) {
    int bi = blockIdx.x;                 // b * select_num + i
    int b = bi / select_num;
    int p = g_patch[b * 64 + (bi % select_num)];
    out_sel[(size_t)bi * (D_ / 4) + threadIdx.x] =
        hid[((size_t)b * N_ + p) * (D_ / 4) + threadIdx.x];
}

// ---------------- launch ----------------
extern "C" void kernel_launch(void* const* d_in, const int* in_sizes, int n_in,
                              void* d_out, int out_size) {
    const float* hid = (const float*)d_in[0];
    const float* x   = (const float*)d_in[1];
    const float* w1  = (const float*)d_in[2];
    const float* w2  = (const float*)d_in[3];
    float* out = (float*)d_out;

    // out = [hs (B,N,D)] ++ [selected (B,sn,D)]
    int sn = (out_size - B_ * N_ * D_) / (B_ * D_);
    if (sn < 1) sn = 1;
    if (sn > 64) sn = 64;

    k_zero<<<8, 784>>>();
    k_score<<<B_ * C_, S_>>>(x);
    k_batch<<<B_, 1024>>>();
    k_gcn<<<B_, D_>>>(w1, w2);

    const int TOT4 = B_ * N_ * (D_ / 4);
    k_hs<<<(TOT4 + 255) / 256, 256>>>((const float4*)hid, (float4*)out);

    k_order<<<B_, S_>>>(sn);
    k_gather<<<B_ * sn, D_ / 4>>>((const float4*)hid,
                                  (float4*)(out + (size_t)B_ * N_ * D_), sn);
}

// round 2
// speedup vs baseline: 1.2766x; 1.2766x over previous
#include <cuda_runtime.h>
#include <math.h>

#define B_ 8
#define C_ 12
#define S_ 784
#define N_ 785
#define D_ 768
#define H_ 28
#define PATCHNUM 84
#define NSPLIT 16           // j-splits of the 512-dim GCN contraction
#define JCHUNK (512 / NSPLIT)   // 32
#define DSPLIT 3            // 768 cols / 256 threads

// ---------------- scratch (static __device__, no allocs) ----------------
__device__ float g_newscore[B_ * C_ * S_];
__device__ unsigned char g_sel[B_ * C_ * S_];
__device__ __align__(16) float g_part[NSPLIT * B_ * D_];
__device__ int g_patch[B_ * 64];
struct BSc { float c0, c1, Ppos, Pneg, pwa; int anchor; };
__device__ BSc g_bs[B_];

// ---------------- warp helpers ----------------
__inline__ __device__ float warpSum(float v) {
    #pragma unroll
    for (int o = 16; o > 0; o >>= 1) v += __shfl_down_sync(0xffffffffu, v, o);
    return v;
}

// ---------------- K1: per (b,c) top-84 select + new_score + selection mask
__global__ void k_score(const float* __restrict__ x) {
    int bc = blockIdx.x;           // b*C + c, 96 blocks
    int s  = threadIdx.x;          // 784 threads
    __shared__ float sc[S_];
    float v = x[(size_t)bc * N_ * N_ + 1 + s];   // x[b,c,0,1+s]
    sc[s] = v;
    __syncthreads();
    int r = 0;
    #pragma unroll 8
    for (int t = 0; t < S_; t++) {
        float o = sc[t];
        r += (o > v) || (o == v && t < s);
    }
    bool sel = (r < PATCHNUM);
    g_newscore[bc * S_ + s] = sel ? v : 0.7f * v;
    g_sel[bc * S_ + s] = sel ? 1 : 0;
}

// ---------------- K2: per-batch reductions (warp-shuffle based)
__global__ void k_batch() {
    int b = blockIdx.x, tid = threadIdx.x;      // 1024 threads, 32 warps
    int lane = tid & 31, wid = tid >> 5;
    __shared__ float pw[S_];
    __shared__ float sred[32];
    __shared__ int   sidx[32];
    __shared__ float s4[32 * 4];
    __shared__ float sMean;
    __shared__ int   sAnchor;

    float m = 0.f;
    if (tid < S_) {
        #pragma unroll
        for (int c = 0; c < C_; c++) m += g_newscore[(b * C_ + c) * S_ + tid];
        pw[tid] = m * (1.0f / 12.0f);
    }
    // ---- mean of m ----
    float t = (tid < S_) ? m : 0.f;
    t = warpSum(t);
    if (lane == 0) sred[wid] = t;
    __syncthreads();
    if (tid < 32) {
        float x2 = warpSum(sred[tid]);
        if (tid == 0) sMean = x2 * (1.0f / 784.0f);
    }
    __syncthreads();
    float mean = sMean;

    // ---- argmax of binary*pw (first index on ties) ----
    float mv = -1e30f; int mi = tid;
    if (tid < S_) mv = (m > mean) ? pw[tid] : 0.0f;
    #pragma unroll
    for (int o = 16; o > 0; o >>= 1) {
        float ov = __shfl_down_sync(0xffffffffu, mv, o);
        int   oi = __shfl_down_sync(0xffffffffu, mi, o);
        if (ov > mv || (ov == mv && oi < mi)) { mv = ov; mi = oi; }
    }
    if (lane == 0) { sred[wid] = mv; sidx[wid] = mi; }
    __syncthreads();
    if (tid < 32) {
        mv = sred[tid]; mi = sidx[tid];
        #pragma unroll
        for (int o = 16; o > 0; o >>= 1) {
            float ov = __shfl_down_sync(0xffffffffu, mv, o);
            int   oi = __shfl_down_sync(0xffffffffu, mi, o);
            if (ov > mv || (ov == mv && oi < mi)) { mv = ov; mi = oi; }
        }
        if (tid == 0) sAnchor = mi;
    }
    __syncthreads();
    int anchor = sAnchor;

    // ---- 4 structure sums ----
    float p = 0.f, d = 0.f, a = 0.f;
    if (tid < S_) {
        p = pw[tid];
        int ai = anchor / H_, aj = anchor % H_;
        float r0 = (float)(tid / H_ - ai) * (1.0f / (float)H_);
        float r1 = (float)(tid % H_ - aj) * (1.0f / (float)H_);
        d = sqrtf(r0 * r0 + r1 * r1);
        a = (atan2f(r1, r0) * (1.0f / 3.14159265358979323846f) + 1.0f) * 0.5f;
    }
    float vals[4] = { p * d, p * a, (p > 0.f) ? p * p : 0.f, (p < 0.f) ? p * p : 0.f };
    #pragma unroll
    for (int k = 0; k < 4; k++) {
        float w = warpSum(vals[k]);
        if (lane == 0) s4[wid * 4 + k] = w;
    }
    __syncthreads();
    if (tid < 32) {
        float o0 = warpSum(s4[tid * 4 + 0]);
        float o1 = warpSum(s4[tid * 4 + 1]);
        float o2 = warpSum(s4[tid * 4 + 2]);
        float o3 = warpSum(s4[tid * 4 + 3]);
        if (tid == 0) {
            BSc bs;
            bs.c0 = o0; bs.c1 = o1; bs.Ppos = o2; bs.Pneg = o3;
            bs.pwa = pw[anchor]; bs.anchor = anchor;
            g_bs[b] = bs;
        }
    }
}

// ---------------- K3: split-K collapsed GCN, all batches per w2 tile
__global__ void k_gcnp(const float* __restrict__ w1, const float* __restrict__ w2) {
    int js = blockIdx.x / DSPLIT;          // 0..15
    int ds = blockIdx.x % DSPLIT;          // 0..2
    int tid = threadIdx.x;                 // 256 threads
    __shared__ float su[8][JCHUNK];

    {   // thread t: j = t%32 within chunk, b = t/32
        int j = js * JCHUNK + (tid & (JCHUNK - 1));
        int b = tid >> 5;
        BSc bs = g_bs[b];
        float v = bs.c0 * w1[j] + bs.c1 * w1[512 + j];
        su[b][tid & (JCHUNK - 1)] = bs.Ppos * fmaxf(v, 0.f) + bs.Pneg * fminf(v, 0.f);
    }
    __syncthreads();

    int col = ds * 256 + tid;
    float acc[8] = {0.f, 0.f, 0.f, 0.f, 0.f, 0.f, 0.f, 0.f};
    #pragma unroll
    for (int jj = 0; jj < JCHUNK; jj++) {
        float w = w2[(js * JCHUNK + jj) * D_ + col];
        #pragma unroll
        for (int b = 0; b < 8; b++) acc[b] += su[b][jj] * w;
    }
    #pragma unroll
    for (int b = 0; b < 8; b++) g_part[(js * 8 + b) * D_ + col] = acc[b];
}

// ---------------- K4: hs = hidden_states; row 0 gets finalized GCN output
__global__ void k_hs(const float4* __restrict__ hid, float4* __restrict__ out) {
    const int TOT4 = B_ * N_ * (D_ / 4);   // 1,205,760
    int i = blockIdx.x * blockDim.x + threadIdx.x;
    if (i >= TOT4) return;
    float4 v = hid[i];
    int row = i / (D_ / 4);
    int n = row % N_;
    if (n == 0) {
        int b  = row / N_;
        int d4 = i % (D_ / 4);
        float4 acc = make_float4(0.f, 0.f, 0.f, 0.f);
        #pragma unroll
        for (int js = 0; js < NSPLIT; js++) {
            float4 pv = ((const float4*)g_part)[(js * 8 + b) * (D_ / 4) + d4];
            acc.x += pv.x; acc.y += pv.y; acc.z += pv.z; acc.w += pv.w;
        }
        float pwa = g_bs[b].pwa;
        float ox = pwa * acc.x, oy = pwa * acc.y, oz = pwa * acc.z, ow = pwa * acc.w;
        v.x += (ox > 0.f) ? ox : 0.2f * ox;
        v.y += (oy > 0.f) ? oy : 0.2f * oy;
        v.z += (oz > 0.f) ? oz : 0.2f * oz;
        v.w += (ow > 0.f) ? ow : 0.2f * ow;
    }
    out[i] = v;
}

// ---------------- K5: counts from sel mask + 3x3 conv + exact stable rank
__global__ void k_order(int select_num) {
    int b = blockIdx.x, s = threadIdx.x;   // 784 threads
    __shared__ int cnt[S_];
    __shared__ int conv[S_];
    int c0 = 0;
    #pragma unroll
    for (int c = 0; c < C_; c++) c0 += g_sel[(b * C_ + c) * S_ + s];
    cnt[s] = c0;
    __syncthreads();
    int i = s / H_, j = s % H_;
    int acc = 0;
    #pragma unroll
    for (int di = -1; di <= 1; di++) {
        #pragma unroll
        for (int dj = -1; dj <= 1; dj++) {
            int ii = i + di, jj = j + dj;
            if (ii >= 0 && ii < H_ && jj >= 0 && jj < H_) {
                int w = (di == 0 ? 2 : 1) * (dj == 0 ? 2 : 1);
                acc += w * cnt[ii * H_ + jj];
            }
        }
    }
    conv[s] = acc;
    __syncthreads();
    int r = 0;
    #pragma unroll 8
    for (int t = 0; t < S_; t++) {
        int o = conv[t];
        r += (o > acc) || (o == acc && t < s);
    }
    if (r < select_num && r < 64) g_patch[b * 64 + r] = s + 1;
}

// ---------------- K6: gather selected rows (indices >= 1 -> raw hidden_states)
__global__ void k_gather(const float4* __restrict__ hid, float4* __restrict__ out_sel,
                         int select_num) {
    int bi = blockIdx.x;                 // b * select_num + i
    int b = bi / select_num;
    int p = g_patch[b * 64 + (bi % select_num)];
    out_sel[(size_t)bi * (D_ / 4) + threadIdx.x] =
        hid[((size_t)b * N_ + p) * (D_ / 4) + threadIdx.x];
}

// ---------------- launch ----------------
extern "C" void kernel_launch(void* const* d_in, const int* in_sizes, int n_in,
                              void* d_out, int out_size) {
    const float* hid = (const float*)d_in[0];
    const float* x   = (const float*)d_in[1];
    const float* w1  = (const float*)d_in[2];
    const float* w2  = (const float*)d_in[3];
    float* out = (float*)d_out;

    int sn = (out_size - B_ * N_ * D_) / (B_ * D_);
    if (sn < 1) sn = 1;
    if (sn > 64) sn = 64;

    k_score<<<B_ * C_, S_>>>(x);
    k_batch<<<B_, 1024>>>();
    k_gcnp<<<NSPLIT * DSPLIT, 256>>>(w1, w2);

    const int TOT4 = B_ * N_ * (D_ / 4);
    k_hs<<<(TOT4 + 255) / 256, 256>>>((const float4*)hid, (float4*)out);

    k_order<<<B_, S_>>>(sn);
    k_gather<<<B_ * sn, D_ / 4>>>((const float4*)hid,
                                  (float4*)(out + (size_t)B_ * N_ * D_), sn);
}

// round 3
// speedup vs baseline: 3.1340x; 2.4549x over previous
#include <cuda_runtime.h>
#include <math.h>

#define B_ 8
#define C_ 12
#define S_ 784
#define N_ 785
#define D_ 768
#define H_ 28
#define PATCHNUM 84
#define NSPLIT 16
#define JCHUNK (512 / NSPLIT)   // 32
#define DSPLIT 3

typedef unsigned long long u64;

// ---------------- scratch ----------------
__device__ float g_newscore[B_ * C_ * S_];
__device__ unsigned char g_sel[B_ * C_ * S_];
__device__ __align__(16) float g_part[NSPLIT * B_ * D_];
__device__ int g_patch[B_ * 64];
struct BSc { float c0, c1, Ppos, Pneg, pwa; int anchor; };
__device__ BSc g_bs[B_];

__inline__ __device__ float warpSum(float v) {
    #pragma unroll
    for (int o = 16; o > 0; o >>= 1) v += __shfl_down_sync(0xffffffffu, v, o);
    return v;
}

// ---------------- K1: top-84 select via 2-level radix on ordered float bits
__global__ void k_score(const float* __restrict__ x) {
    int bc = blockIdx.x;           // 96 blocks
    int s  = threadIdx.x;          // 784 threads
    __shared__ int hist[256];
    __shared__ int pref[256];
    __shared__ int hist2[256];
    __shared__ u64 carr[S_];
    __shared__ int ccnt;

    float v = x[(size_t)bc * N_ * N_ + 1 + s];
    unsigned u = __float_as_uint(v);
    unsigned ou = u ^ ((u & 0x80000000u) ? 0xFFFFFFFFu : 0x80000000u); // monotonic

    if (s < 256) { hist[s] = 0; hist2[s] = 0; }
    if (s == 0) ccnt = 0;
    __syncthreads();
    atomicAdd(&hist[ou >> 24], 1);
    __syncthreads();
    // inclusive suffix sums: pref[b] = #elems with top byte >= b
    if (s < 256) pref[s] = hist[s];
    __syncthreads();
    #pragma unroll
    for (int off = 1; off < 256; off <<= 1) {
        int val = 0;
        if (s < 256) { val = pref[s]; if (s + off < 256) val += pref[s + off]; }
        __syncthreads();
        if (s < 256) pref[s] = val;
        __syncthreads();
    }
    int b1 = ou >> 24;
    int gt1 = (b1 < 255) ? pref[b1 + 1] : 0;   // strictly greater bucket count
    int ge1 = pref[b1];
    bool sel = (ge1 <= PATCHNUM);               // whole bucket inside top-84
    bool bd1 = (gt1 < PATCHNUM) && (ge1 > PATCHNUM);
    // level 2 within boundary bucket
    if (bd1) atomicAdd(&hist2[(ou >> 16) & 255], 1);
    __syncthreads();
    if (s < 256) pref[s] = hist2[s];
    __syncthreads();
    #pragma unroll
    for (int off = 1; off < 256; off <<= 1) {
        int val = 0;
        if (s < 256) { val = pref[s]; if (s + off < 256) val += pref[s + off]; }
        __syncthreads();
        if (s < 256) pref[s] = val;
        __syncthreads();
    }
    u64 key = ((u64)ou << 10) | (u64)(1023 - s);
    bool bd2 = false;
    int gt2 = 0;
    if (bd1) {
        int b2 = (ou >> 16) & 255;
        gt2 = gt1 + ((b2 < 255) ? pref[b2 + 1] : 0);
        int ge2 = gt1 + pref[b2];
        if (gt2 >= PATCHNUM)       sel = false;
        else if (ge2 <= PATCHNUM)  sel = true;
        else                       bd2 = true;
    }
    if (bd2) { int ix = atomicAdd(&ccnt, 1); carr[ix] = key; }
    __syncthreads();
    int m = ccnt;
    if (bd2) {
        int r = gt2;
        for (int i = 0; i < m; i++) r += (carr[i] > key);
        sel = (r < PATCHNUM);
    }
    g_newscore[bc * S_ + s] = sel ? v : 0.7f * v;
    g_sel[bc * S_ + s] = sel ? 1 : 0;
}

// ---------------- K2: per-batch reductions (warp shuffles)
__global__ void k_batch() {
    int b = blockIdx.x, tid = threadIdx.x;      // 1024 threads
    int lane = tid & 31, wid = tid >> 5;
    __shared__ float pw[S_];
    __shared__ float sred[32];
    __shared__ int   sidx[32];
    __shared__ float s4[32 * 4];
    __shared__ float sMean;
    __shared__ int   sAnchor;

    float m = 0.f;
    if (tid < S_) {
        #pragma unroll
        for (int c = 0; c < C_; c++) m += g_newscore[(b * C_ + c) * S_ + tid];
        pw[tid] = m * (1.0f / 12.0f);
    }
    float t = (tid < S_) ? m : 0.f;
    t = warpSum(t);
    if (lane == 0) sred[wid] = t;
    __syncthreads();
    if (tid < 32) {
        float x2 = warpSum(sred[tid]);
        if (tid == 0) sMean = x2 * (1.0f / 784.0f);
    }
    __syncthreads();
    float mean = sMean;

    float mv = -1e30f; int mi = tid;
    if (tid < S_) mv = (m > mean) ? pw[tid] : 0.0f;
    #pragma unroll
    for (int o = 16; o > 0; o >>= 1) {
        float ov = __shfl_down_sync(0xffffffffu, mv, o);
        int   oi = __shfl_down_sync(0xffffffffu, mi, o);
        if (ov > mv || (ov == mv && oi < mi)) { mv = ov; mi = oi; }
    }
    if (lane == 0) { sred[wid] = mv; sidx[wid] = mi; }
    __syncthreads();
    if (tid < 32) {
        mv = sred[tid]; mi = sidx[tid];
        #pragma unroll
        for (int o = 16; o > 0; o >>= 1) {
            float ov = __shfl_down_sync(0xffffffffu, mv, o);
            int   oi = __shfl_down_sync(0xffffffffu, mi, o);
            if (ov > mv || (ov == mv && oi < mi)) { mv = ov; mi = oi; }
        }
        if (tid == 0) sAnchor = mi;
    }
    __syncthreads();
    int anchor = sAnchor;

    float p = 0.f, d = 0.f, a = 0.f;
    if (tid < S_) {
        p = pw[tid];
        int ai = anchor / H_, aj = anchor % H_;
        float r0 = (float)(tid / H_ - ai) * (1.0f / (float)H_);
        float r1 = (float)(tid % H_ - aj) * (1.0f / (float)H_);
        d = sqrtf(r0 * r0 + r1 * r1);
        a = (atan2f(r1, r0) * (1.0f / 3.14159265358979323846f) + 1.0f) * 0.5f;
    }
    float vals[4] = { p * d, p * a, (p > 0.f) ? p * p : 0.f, (p < 0.f) ? p * p : 0.f };
    #pragma unroll
    for (int k = 0; k < 4; k++) {
        float w = warpSum(vals[k]);
        if (lane == 0) s4[wid * 4 + k] = w;
    }
    __syncthreads();
    if (tid < 32) {
        float o0 = warpSum(s4[tid * 4 + 0]);
        float o1 = warpSum(s4[tid * 4 + 1]);
        float o2 = warpSum(s4[tid * 4 + 2]);
        float o3 = warpSum(s4[tid * 4 + 3]);
        if (tid == 0) {
            BSc bs;
            bs.c0 = o0; bs.c1 = o1; bs.Ppos = o2; bs.Pneg = o3;
            bs.pwa = pw[anchor]; bs.anchor = anchor;
            g_bs[b] = bs;
        }
    }
}

// ---------------- K3: split-K collapsed GCN
__global__ void k_gcnp(const float* __restrict__ w1, const float* __restrict__ w2) {
    int js = blockIdx.x / DSPLIT;
    int ds = blockIdx.x % DSPLIT;
    int tid = threadIdx.x;                 // 256
    __shared__ float su[8][JCHUNK];
    {
        int j = js * JCHUNK + (tid & (JCHUNK - 1));
        int b = tid >> 5;
        BSc bs = g_bs[b];
        float v = bs.c0 * w1[j] + bs.c1 * w1[512 + j];
        su[b][tid & (JCHUNK - 1)] = bs.Ppos * fmaxf(v, 0.f) + bs.Pneg * fminf(v, 0.f);
    }
    __syncthreads();
    int col = ds * 256 + tid;
    float acc[8] = {0.f,0.f,0.f,0.f,0.f,0.f,0.f,0.f};
    #pragma unroll
    for (int jj = 0; jj < JCHUNK; jj++) {
        float w = w2[(js * JCHUNK + jj) * D_ + col];
        #pragma unroll
        for (int b = 0; b < 8; b++) acc[b] += su[b][jj] * w;
    }
    #pragma unroll
    for (int b = 0; b < 8; b++) g_part[(js * 8 + b) * D_ + col] = acc[b];
}

// ---------------- K4: copy, grid (N, B), no div/mod
__global__ void k_hs(const float4* __restrict__ hid, float4* __restrict__ out) {
    int i = (blockIdx.y * N_ + blockIdx.x) * (D_ / 4) + threadIdx.x;  // block 192
    float4 v = hid[i];
    if (blockIdx.x == 0) {
        int b = blockIdx.y;
        int d4 = threadIdx.x;
        float4 acc = make_float4(0.f, 0.f, 0.f, 0.f);
        #pragma unroll
        for (int js = 0; js < NSPLIT; js++) {
            float4 pv = ((const float4*)g_part)[(js * 8 + b) * (D_ / 4) + d4];
            acc.x += pv.x; acc.y += pv.y; acc.z += pv.z; acc.w += pv.w;
        }
        float pwa = g_bs[b].pwa;
        float ox = pwa * acc.x, oy = pwa * acc.y, oz = pwa * acc.z, ow = pwa * acc.w;
        v.x += (ox > 0.f) ? ox : 0.2f * ox;
        v.y += (oy > 0.f) ? oy : 0.2f * oy;
        v.z += (oz > 0.f) ? oz : 0.2f * oz;
        v.w += (ow > 0.f) ? ow : 0.2f * ow;
    }
    out[i] = v;
}

// ---------------- K5: conv + counting-sort rank (exact, stable-descending)
__global__ void k_order(int select_num) {
    int b = blockIdx.x, s = threadIdx.x;   // 784
    __shared__ int cnt[S_];
    __shared__ int hist[256];
    __shared__ int pref[256];
    __shared__ u64 carr[S_];
    __shared__ int ccnt;

    int c0 = 0;
    #pragma unroll
    for (int c = 0; c < C_; c++) c0 += g_sel[(b * C_ + c) * S_ + s];
    cnt[s] = c0;
    if (s < 256) hist[s] = 0;
    if (s == 0) ccnt = 0;
    __syncthreads();

    int i = s / H_, j = s % H_;
    int acc = 0;
    #pragma unroll
    for (int di = -1; di <= 1; di++) {
        #pragma unroll
        for (int dj = -1; dj <= 1; dj++) {
            int ii = i + di, jj = j + dj;
            if (ii >= 0 && ii < H_ && jj >= 0 && jj < H_) {
                int w = (di == 0 ? 2 : 1) * (dj == 0 ? 2 : 1);
                acc += w * cnt[ii * H_ + jj];
            }
        }
    }
    atomicAdd(&hist[acc], 1);   // acc <= 192
    __syncthreads();
    if (s < 256) pref[s] = hist[s];
    __syncthreads();
    #pragma unroll
    for (int off = 1; off < 256; off <<= 1) {
        int val = 0;
        if (s < 256) { val = pref[s]; if (s + off < 256) val += pref[s + off]; }
        __syncthreads();
        if (s < 256) pref[s] = val;
        __syncthreads();
    }
    int gtv = (acc < 255) ? pref[acc + 1] : 0;   // #elems strictly greater
    bool cand = (gtv < select_num);
    u64 key = ((u64)(unsigned)acc << 10) | (u64)(1023 - s);
    if (cand) { int ix = atomicAdd(&ccnt, 1); carr[ix] = key; }
    __syncthreads();
    int m = ccnt;
    if (cand) {
        int r = 0;
        for (int t = 0; t < m; t++) r += (carr[t] > key);
        if (r < select_num) g_patch[b * 64 + r] = s + 1;
    }
}

// ---------------- K6: gather selected rows
__global__ void k_gather(const float4* __restrict__ hid, float4* __restrict__ out_sel,
                         int select_num) {
    int bi = blockIdx.x;
    int b = bi / select_num;
    int p = g_patch[b * 64 + (bi % select_num)];
    out_sel[(size_t)bi * (D_ / 4) + threadIdx.x] =
        hid[((size_t)b * N_ + p) * (D_ / 4) + threadIdx.x];
}

// ---------------- launch ----------------
extern "C" void kernel_launch(void* const* d_in, const int* in_sizes, int n_in,
                              void* d_out, int out_size) {
    const float* hid = (const float*)d_in[0];
    const float* x   = (const float*)d_in[1];
    const float* w1  = (const float*)d_in[2];
    const float* w2  = (const float*)d_in[3];
    float* out = (float*)d_out;

    int sn = (out_size - B_ * N_ * D_) / (B_ * D_);
    if (sn < 1) sn = 1;
    if (sn > 64) sn = 64;

    k_score<<<B_ * C_, S_>>>(x);
    k_batch<<<B_, 1024>>>();
    k_gcnp<<<NSPLIT * DSPLIT, 256>>>(w1, w2);
    k_hs<<<dim3(N_, B_), D_ / 4>>>((const float4*)hid, (float4*)out);
    k_order<<<B_, S_>>>(sn);
    k_gather<<<B_ * sn, D_ / 4>>>((const float4*)hid,
                                  (float4*)(out + (size_t)B_ * N_ * D_), sn);
}